// round 2
// baseline (speedup 1.0000x reference)
#include <cuda_runtime.h>
#include <cstdint>

#define IN_F   2048
#define OUT_F  512
#define NBITS  8
#define BATCH  8
#define F4     (IN_F / 4)   // 512 packed-uint32 rows

// 1 MB packed-bit scratch: g_W[f4 * OUT_F + o] holds bytes for f = 4*f4 .. 4*f4+3,
// byte bit k = (weight[f, o*8+k] >= 0.5)
__device__ uint32_t g_W[F4 * OUT_F];

// ---------------------------------------------------------------------------
// Kernel A: binarize + pack weights. One thread per output uint32.
// ---------------------------------------------------------------------------
__global__ void pack_bits_kernel(const float* __restrict__ weight) {
    int tid = blockIdx.x * blockDim.x + threadIdx.x;
    if (tid >= F4 * OUT_F) return;
    int o  = tid & (OUT_F - 1);
    int f4 = tid >> 9;               // / OUT_F
    uint32_t word = 0;
#pragma unroll
    for (int j = 0; j < 4; ++j) {
        int f = f4 * 4 + j;
        const float4* wp =
            reinterpret_cast<const float4*>(weight + (size_t)f * (OUT_F * NBITS) + (size_t)o * NBITS);
        float4 w0 = wp[0];
        float4 w1 = wp[1];
        uint32_t byte = 0;
        byte |= (w0.x >= 0.5f) ? 1u   : 0u;
        byte |= (w0.y >= 0.5f) ? 2u   : 0u;
        byte |= (w0.z >= 0.5f) ? 4u   : 0u;
        byte |= (w0.w >= 0.5f) ? 8u   : 0u;
        byte |= (w1.x >= 0.5f) ? 16u  : 0u;
        byte |= (w1.y >= 0.5f) ? 32u  : 0u;
        byte |= (w1.z >= 0.5f) ? 64u  : 0u;
        byte |= (w1.w >= 0.5f) ? 128u : 0u;
        word |= byte << (8 * j);
    }
    g_W[tid] = word;
}

// ---------------------------------------------------------------------------
// Kernel B: the carry-save-adder scan. One thread per (b, o) pair.
// State kept HALVED (s~ = s/2, x~ = x/2, c~ = h/2) so:
//   p~ = s~ (+ x~ if bit)          -- matches round((s+a)/2) = round(s+a)/2
//   t~ = p~ + c~                   -- matches t/2
//   h  = floorf(t~)                -- = floor(t/2), integer, UNscaled
//   s~' = t~ - h                   -- exact; = (t - 2h)/2
//   c~'[k] = 0.5f * h[k-1]         -- off the critical chain
// Final outputs are 2*s~ and [0, h0..h6] (= 2*c~).  Bit-identical to reference.
// ---------------------------------------------------------------------------
__global__ __launch_bounds__(32, 1)
void csa_kernel(const float* __restrict__ x, float* __restrict__ out) {
    __shared__ float xs[IN_F];

    const int lane = threadIdx.x;
    const int b    = blockIdx.x >> 4;    // 128 blocks: 8 b's x 16 o-groups
    const int og   = blockIdx.x & 15;
    const int o    = og * 32 + lane;

    // Stage halved x row into shared
    const float* xrow = x + (size_t)b * IN_F;
    for (int i = lane; i < IN_F; i += 32) xs[i] = 0.5f * xrow[i];
    __syncthreads();

    float s[8], c[8];
#pragma unroll
    for (int k = 0; k < 8; ++k) { s[k] = 0.0f; c[k] = 0.0f; }

    // Software-pipelined packed-bit loads (depth 2) + x prefetch (depth 1)
    const uint32_t* Wp = g_W + o;
    uint32_t w0 = Wp[0];
    uint32_t w1 = Wp[OUT_F];
    float xc[4];
#pragma unroll
    for (int j = 0; j < 4; ++j) xc[j] = xs[j];

    for (int f4 = 0; f4 < F4; ++f4) {
        uint32_t w = w0;
        w0 = w1;
        int nid = f4 + 2; if (nid > F4 - 1) nid = F4 - 1;
        w1 = Wp[(size_t)nid * OUT_F];

        float xn[4];
        int xf = (f4 + 1 < F4) ? (f4 + 1) * 4 : f4 * 4;
#pragma unroll
        for (int j = 0; j < 4; ++j) xn[j] = xs[xf + j];

#pragma unroll
        for (int j = 0; j < 4; ++j) {
            const float    xh   = xc[j];
            const unsigned byte = (w >> (8 * j)) & 0xffu;
            float h[8];
#pragma unroll
            for (int k = 0; k < 8; ++k) {
                float sv = s[k];
                unsigned bit = byte & (1u << k);
                // predicated add: when bit==0, sv unchanged (== s + 0, exact)
                asm("{\n\t"
                    ".reg .pred p;\n\t"
                    "setp.ne.u32 p, %1, 0;\n\t"
                    "@p add.f32 %0, %0, %2;\n\t"
                    "}" : "+f"(sv) : "r"(bit), "f"(xh));
                float tv = (k == 0) ? sv : (sv + c[k]);   // lane0 carry-in is always 0
                float hv = floorf(tv);
                h[k] = hv;
                s[k] = tv - hv;                            // exact
            }
#pragma unroll
            for (int k = 7; k >= 1; --k) c[k] = 0.5f * h[k - 1];
        }
#pragma unroll
        for (int j = 0; j < 4; ++j) xc[j] = xn[j];
    }

    // Outputs: s block [B, O*8] then carry block [B*O, 8]; both index pair*8+k.
    const int pair = b * OUT_F + o;
    float4* so = reinterpret_cast<float4*>(out + (size_t)pair * 8);
    so[0] = make_float4(2.0f * s[0], 2.0f * s[1], 2.0f * s[2], 2.0f * s[3]);
    so[1] = make_float4(2.0f * s[4], 2.0f * s[5], 2.0f * s[6], 2.0f * s[7]);
    float4* co = reinterpret_cast<float4*>(out + (size_t)(BATCH * OUT_F * NBITS) + (size_t)pair * 8);
    co[0] = make_float4(0.0f,        2.0f * c[1], 2.0f * c[2], 2.0f * c[3]);
    co[1] = make_float4(2.0f * c[4], 2.0f * c[5], 2.0f * c[6], 2.0f * c[7]);
}

// ---------------------------------------------------------------------------
extern "C" void kernel_launch(void* const* d_in, const int* in_sizes, int n_in,
                              void* d_out, int out_size) {
    const float* x = (const float*)d_in[0];
    const float* w = (const float*)d_in[1];
    // defensive: x has 16384 elems, weight has 8388608
    if (n_in >= 2 && in_sizes[0] > in_sizes[1]) {
        const float* t = x; x = w; w = t;
    }
    float* out = (float*)d_out;

    pack_bits_kernel<<<(F4 * OUT_F + 255) / 256, 256>>>(w);
    csa_kernel<<<BATCH * 16, 32>>>(x, out);
}

// round 7
// speedup vs baseline: 2.7554x; 2.7554x over previous
#include <cuda_runtime.h>
#include <cstdint>

#define IN_F   2048
#define OUT_F  512
#define NBITS  8
#define BATCH  8
#define NFB    (IN_F / 16)        // 128 f-blocks, 16 f per packed word
#define WCOLS  (OUT_F * 4)        // 2048 words per f-block row (one per (o,sub))

// 1 MB packed bits: g_W2[fb*WCOLS + o*4 + sub]
// bit (2j+i) of word = (weight[16*fb+j, o*8 + 2*sub + i] >= 0.5)
__device__ uint32_t g_W2[NFB * WCOLS];

// ---------------------------------------------------------------------------
// Kernel A: binarize + pack. One thread per output word (262144 threads).
// Consecutive threads read consecutive float2 -> fully coalesced; DRAM-bound.
// ---------------------------------------------------------------------------
__global__ void pack2_kernel(const float* __restrict__ weight) {
    int tid = blockIdx.x * blockDim.x + threadIdx.x;
    if (tid >= NFB * WCOLS) return;
    int o4 = tid & (WCOLS - 1);       // o*4 + sub ; col = 2*o4
    int fb = tid >> 11;               // / WCOLS
    const float2* wp = reinterpret_cast<const float2*>(weight);
    uint32_t word = 0;
#pragma unroll
    for (int j = 0; j < 16; ++j) {
        int f = fb * 16 + j;
        float2 v = wp[(size_t)f * (OUT_F * NBITS / 2) + o4];
        word |= (v.x >= 0.5f ? 1u : 0u) << (2 * j);
        word |= (v.y >= 0.5f ? 1u : 0u) << (2 * j + 1);
    }
    g_W2[tid] = word;
}

// ---------------------------------------------------------------------------
// Kernel B: carry-save-adder scan, 4 threads per (b,o) pair, 2 bit-lanes each.
// All state HALVED (s~=s/2, x~=x/2, c~=h/2); on t~ in [0,2):
//   t~  = (s~ + a~) + c~            (a~ = x~ or +0  -> FADD identical to ref)
//   p   = (t~ >= 1)                 (== floor(t~) since t~ < 2)
//   s~' = p ? t~-1 : t~             (Sterbenz-exact == t~ - floor(t~))
//   c~' = p ? 0.5 : 0               (next step's halved carry)
// Lane k's carry-in = previous step's c~ of lane k-1:
//   lane1 <- own lane0 (register), lane0 <- SHFL.UP of neighbor's lane1
// (feed-forward pipeline across threads, not a dependence cycle).
// Bit-identical to the reference (R1 validated the same algebra at rel_err 0).
// ---------------------------------------------------------------------------
__global__ __launch_bounds__(128, 1)
void csa2_kernel(const float* __restrict__ x, float* __restrict__ out) {
    __shared__ float4 xs4[IN_F / 4];

    const int tid = threadIdx.x;
    const int sub = tid & 3;           // which lane-pair of the 8 bit lanes
    const int pl  = tid >> 2;          // pair index within block (0..31)
    const int b   = blockIdx.x >> 4;   // 128 blocks = 8 b * 16 o-groups
    const int og  = blockIdx.x & 15;
    const int o   = og * 32 + pl;

    // Stage halved x row into shared (vectorized)
    const float4* xr4 = reinterpret_cast<const float4*>(x + (size_t)b * IN_F);
    for (int i = tid; i < IN_F / 4; i += 128) {
        float4 v = xr4[i];
        v.x *= 0.5f; v.y *= 0.5f; v.z *= 0.5f; v.w *= 0.5f;
        xs4[i] = v;
    }
    __syncthreads();

    const uint32_t* Wp = g_W2 + (o * 4 + sub);
    const unsigned zmask = (sub == 0) ? 0u : 0xffffffffu;  // lane0 of pair: carry-in 0

    float s0 = 0.0f, s1 = 0.0f;
    float c01 = 0.0f;   // prev step's cn0 (carry lane k0 -> lane k1)
    float shv = 0.0f;   // prev step's cn1 of thread sub-1 (carry -> lane k0)

    uint32_t w  = Wp[0];
    uint32_t wn = Wp[WCOLS];

    for (int fb = 0; fb < NFB; ++fb) {
        const uint32_t wcur = w;
        w = wn;
        int nid = (fb + 2 < NFB) ? (fb + 2) : (NFB - 1);
        wn = Wp[(size_t)nid * WCOLS];

#pragma unroll
        for (int q = 0; q < 4; ++q) {
            float4 xv = xs4[fb * 4 + q];          // broadcast LDS.128
            float xq[4] = {xv.x, xv.y, xv.z, xv.w};
#pragma unroll
            for (int r = 0; r < 4; ++r) {
                const int j = q * 4 + r;
                const uint32_t xint = __float_as_uint(xq[r]);
                // a = x~ or +0.0 (exact): bit * x_bits
                const float a0 = __uint_as_float(((wcur >> (2 * j)) & 1u) * xint);
                const float a1 = __uint_as_float(((wcur >> (2 * j + 1)) & 1u) * xint);
                const float cin0 = __uint_as_float(__float_as_uint(shv) & zmask);

                const float t0 = (s0 + a0) + cin0;
                const float t1 = (s1 + a1) + c01;
                const bool  p0 = (t0 >= 1.0f);
                const bool  p1 = (t1 >= 1.0f);
                s0 = p0 ? (t0 - 1.0f) : t0;       // exact frac on [0,2)
                s1 = p1 ? (t1 - 1.0f) : t1;
                const float cn0 = p0 ? 0.5f : 0.0f;
                const float cn1 = p1 ? 0.5f : 0.0f;
                c01 = cn0;
                shv = __shfl_up_sync(0xffffffffu, cn1, 1);
            }
        }
    }

    // Final state: s = 2*s~ ; carry[k] = h[k-1] of last step = 2*c~_in
    const float cin0 = __uint_as_float(__float_as_uint(shv) & zmask);
    const int pair = b * OUT_F + o;
    float2* so = reinterpret_cast<float2*>(out + (size_t)pair * 8 + 2 * sub);
    *so = make_float2(2.0f * s0, 2.0f * s1);
    float2* co = reinterpret_cast<float2*>(
        out + (size_t)(BATCH * OUT_F * NBITS) + (size_t)pair * 8 + 2 * sub);
    *co = make_float2(2.0f * cin0, 2.0f * c01);
}

// ---------------------------------------------------------------------------
extern "C" void kernel_launch(void* const* d_in, const int* in_sizes, int n_in,
                              void* d_out, int out_size) {
    const float* x = (const float*)d_in[0];
    const float* w = (const float*)d_in[1];
    if (n_in >= 2 && in_sizes[0] > in_sizes[1]) {  // defensive: x=16K, weight=8.4M
        const float* t = x; x = w; w = t;
    }
    float* out = (float*)d_out;

    pack2_kernel<<<(NFB * WCOLS + 255) / 256, 256>>>(w);
    csa2_kernel<<<BATCH * 16, 128>>>(x, out);
}